// round 16
// baseline (speedup 1.0000x reference)
#include <cuda_runtime.h>
#include <cstdint>
#include <cstddef>

// Problem constants
#define NB 4
#define NH 8
#define ND 64
#define NE 512
#define NR 512
#define NC 512

// Scratch (device globals; allocation inside kernel_launch is forbidden)
__device__ float g_Q[NB * NR * NE];
__device__ float g_K[NB * NC * NE];
__device__ float g_V[NB * NC * NE];
__device__ float g_logits[(size_t)NB * NH * NR * NC];  // dot -> logits -> weights (in place)
__device__ float g_attn[NB * NR * NE];
__device__ int   g_mask_is_i32;

__device__ __forceinline__ uint32_t f2tf32(float x) {
    uint32_t u;
    asm("cvt.rna.tf32.f32 %0, %1;" : "=r"(u) : "f"(x));
    return u;
}

__device__ __forceinline__ void mma_tf32(
    float& c0, float& c1, float& c2, float& c3,
    uint32_t a0, uint32_t a1, uint32_t a2, uint32_t a3,
    uint32_t b0, uint32_t b1)
{
    asm volatile(
        "mma.sync.aligned.m16n8k8.row.col.f32.tf32.tf32.f32 "
        "{%0,%1,%2,%3}, {%4,%5,%6,%7}, {%8,%9}, {%0,%1,%2,%3};"
        : "+f"(c0), "+f"(c1), "+f"(c2), "+f"(c3)
        : "r"(a0), "r"(a1), "r"(a2), "r"(a3), "r"(b0), "r"(b1));
}

// ---------------------------------------------------------------------------
// Probe mask dtype (bool-as-int32 vs uint8). Reads 256 bytes.
// ---------------------------------------------------------------------------
__global__ void detect_mask_kernel(const unsigned char* __restrict__ m)
{
    int is32 = 1;
    for (int i = 0; i < 256; i++)
        if ((i & 3) != 0 && m[i] != 0) { is32 = 0; break; }
    g_mask_is_i32 = is32;
}

// ---------------------------------------------------------------------------
// Fused Q/K/V projection — TF32 mma, K-tile 32 (Round-15 winner, unchanged).
// ---------------------------------------------------------------------------
__global__ __launch_bounds__(256) void qkv_gemm_tf32(
    const float* __restrict__ row_emb, const float* __restrict__ col_emb,
    const float* __restrict__ Wq, const float* __restrict__ Wk, const float* __restrict__ Wv,
    float* __restrict__ Qo, float* __restrict__ Ko, float* __restrict__ Vo)
{
    int z = blockIdx.z;
    const float* A = (z == 0) ? row_emb : col_emb;
    const float* B = (z == 0) ? Wq : (z == 1) ? Wk : Wv;
    float* C = (z == 0) ? Qo : (z == 1) ? Ko : Vo;

    __shared__ float As[128][36];
    __shared__ float Bs[64][36];

    int tid = threadIdx.x;
    int lane = tid & 31;
    int warp = tid >> 5;
    int wm = warp >> 1;
    int wn = warp & 1;
    int tm = blockIdx.y * 128, tn = blockIdx.x * 64;

    float acc[2][4][4];
#pragma unroll
    for (int mt = 0; mt < 2; mt++)
#pragma unroll
        for (int nt = 0; nt < 4; nt++)
#pragma unroll
            for (int q = 0; q < 4; q++) acc[mt][nt][q] = 0.0f;

    int g = lane >> 2;
    int t4 = lane & 3;

    for (int k0 = 0; k0 < NE; k0 += 32) {
#pragma unroll
        for (int f = tid; f < 1024; f += 256) {
            int row = f >> 3, c = (f & 7) << 2;
            float4 v = *reinterpret_cast<const float4*>(A + (size_t)(tm + row) * NE + k0 + c);
            As[row][c + 0] = __uint_as_float(f2tf32(v.x));
            As[row][c + 1] = __uint_as_float(f2tf32(v.y));
            As[row][c + 2] = __uint_as_float(f2tf32(v.z));
            As[row][c + 3] = __uint_as_float(f2tf32(v.w));
        }
#pragma unroll
        for (int f = tid; f < 512; f += 256) {
            int row = f >> 3, c = (f & 7) << 2;
            float4 v = *reinterpret_cast<const float4*>(B + (size_t)(tn + row) * NE + k0 + c);
            Bs[row][c + 0] = __uint_as_float(f2tf32(v.x));
            Bs[row][c + 1] = __uint_as_float(f2tf32(v.y));
            Bs[row][c + 2] = __uint_as_float(f2tf32(v.z));
            Bs[row][c + 3] = __uint_as_float(f2tf32(v.w));
        }
        __syncthreads();

#pragma unroll
        for (int ks = 0; ks < 32; ks += 8) {
            int kc = ks + t4;
            uint32_t a[2][4], b[4][2];
#pragma unroll
            for (int mt = 0; mt < 2; mt++) {
                int r = wm * 32 + mt * 16 + g;
                a[mt][0] = __float_as_uint(As[r][kc]);
                a[mt][1] = __float_as_uint(As[r + 8][kc]);
                a[mt][2] = __float_as_uint(As[r][kc + 4]);
                a[mt][3] = __float_as_uint(As[r + 8][kc + 4]);
            }
#pragma unroll
            for (int nt = 0; nt < 4; nt++) {
                int n = wn * 32 + nt * 8 + g;
                b[nt][0] = __float_as_uint(Bs[n][kc]);
                b[nt][1] = __float_as_uint(Bs[n][kc + 4]);
            }
#pragma unroll
            for (int mt = 0; mt < 2; mt++)
#pragma unroll
                for (int nt = 0; nt < 4; nt++)
                    mma_tf32(acc[mt][nt][0], acc[mt][nt][1], acc[mt][nt][2], acc[mt][nt][3],
                             a[mt][0], a[mt][1], a[mt][2], a[mt][3], b[nt][0], b[nt][1]);
        }
        __syncthreads();
    }

#pragma unroll
    for (int mt = 0; mt < 2; mt++) {
        int row = tm + wm * 32 + mt * 16 + g;
#pragma unroll
        for (int nt = 0; nt < 4; nt++) {
            int col = tn + wn * 32 + nt * 8 + t4 * 2;
            *reinterpret_cast<float2*>(C + (size_t)row * NE + col) =
                make_float2(acc[mt][nt][0], acc[mt][nt][1]);
            *reinterpret_cast<float2*>(C + (size_t)(row + 8) * NE + col) =
                make_float2(acc[mt][nt][2], acc[mt][nt][3]);
        }
    }
}

// ---------------------------------------------------------------------------
// Generic TF32 NT GEMM, K-tile 32, 128x64 tile (Round-15 winner). qk^T.
// ---------------------------------------------------------------------------
__global__ __launch_bounds__(256) void nt_tf32(
    const float* __restrict__ A, const float* __restrict__ B, float* __restrict__ C,
    int K, int lda, int ldb, int ldc,
    int inner, size_t aOut, size_t aIn, size_t bOut, size_t bIn, size_t cOut, size_t cIn,
    float alpha)
{
    int z = blockIdx.z;
    int zo = z / inner, zi = z - zo * inner;
    A += zo * aOut + zi * aIn;
    B += zo * bOut + zi * bIn;
    C += zo * cOut + zi * cIn;

    __shared__ float As[128][36];
    __shared__ float Bs[64][36];

    int tid = threadIdx.x;
    int lane = tid & 31;
    int warp = tid >> 5;
    int wm = warp >> 1;
    int wn = warp & 1;
    int tm = blockIdx.y * 128, tn = blockIdx.x * 64;

    float acc[2][4][4];
#pragma unroll
    for (int mt = 0; mt < 2; mt++)
#pragma unroll
        for (int nt = 0; nt < 4; nt++)
#pragma unroll
            for (int q = 0; q < 4; q++) acc[mt][nt][q] = 0.0f;

    int g = lane >> 2;
    int t4 = lane & 3;

    for (int k0 = 0; k0 < K; k0 += 32) {
#pragma unroll
        for (int f = tid; f < 1024; f += 256) {
            int row = f >> 3, c = (f & 7) << 2;
            float4 v = *reinterpret_cast<const float4*>(A + (size_t)(tm + row) * lda + k0 + c);
            As[row][c + 0] = __uint_as_float(f2tf32(v.x));
            As[row][c + 1] = __uint_as_float(f2tf32(v.y));
            As[row][c + 2] = __uint_as_float(f2tf32(v.z));
            As[row][c + 3] = __uint_as_float(f2tf32(v.w));
        }
#pragma unroll
        for (int f = tid; f < 512; f += 256) {
            int row = f >> 3, c = (f & 7) << 2;
            float4 v = *reinterpret_cast<const float4*>(B + (size_t)(tn + row) * ldb + k0 + c);
            Bs[row][c + 0] = __uint_as_float(f2tf32(v.x));
            Bs[row][c + 1] = __uint_as_float(f2tf32(v.y));
            Bs[row][c + 2] = __uint_as_float(f2tf32(v.z));
            Bs[row][c + 3] = __uint_as_float(f2tf32(v.w));
        }
        __syncthreads();

#pragma unroll
        for (int ks = 0; ks < 32; ks += 8) {
            int kc = ks + t4;
            uint32_t a[2][4], b[4][2];
#pragma unroll
            for (int mt = 0; mt < 2; mt++) {
                int r = wm * 32 + mt * 16 + g;
                a[mt][0] = __float_as_uint(As[r][kc]);
                a[mt][1] = __float_as_uint(As[r + 8][kc]);
                a[mt][2] = __float_as_uint(As[r][kc + 4]);
                a[mt][3] = __float_as_uint(As[r + 8][kc + 4]);
            }
#pragma unroll
            for (int nt = 0; nt < 4; nt++) {
                int n = wn * 32 + nt * 8 + g;
                b[nt][0] = __float_as_uint(Bs[n][kc]);
                b[nt][1] = __float_as_uint(Bs[n][kc + 4]);
            }
#pragma unroll
            for (int mt = 0; mt < 2; mt++)
#pragma unroll
                for (int nt = 0; nt < 4; nt++)
                    mma_tf32(acc[mt][nt][0], acc[mt][nt][1], acc[mt][nt][2], acc[mt][nt][3],
                             a[mt][0], a[mt][1], a[mt][2], a[mt][3], b[nt][0], b[nt][1]);
        }
        __syncthreads();
    }

#pragma unroll
    for (int mt = 0; mt < 2; mt++) {
        int row = tm + wm * 32 + mt * 16 + g;
#pragma unroll
        for (int nt = 0; nt < 4; nt++) {
            int col = tn + wn * 32 + nt * 8 + t4 * 2;
            *reinterpret_cast<float2*>(C + (size_t)row * ldc + col) =
                make_float2(alpha * acc[mt][nt][0], alpha * acc[mt][nt][1]);
            *reinterpret_cast<float2*>(C + (size_t)(row + 8) * ldc + col) =
                make_float2(alpha * acc[mt][nt][2], alpha * acc[mt][nt][3]);
        }
    }
}

// ---------------------------------------------------------------------------
// TF32 NT GEMM, 64x64 tile, 128 threads, K-tile 32 — outproj (256 CTAs).
// Same warp math as nt_tf32 (2x2 warps of 32x32).
// ---------------------------------------------------------------------------
__global__ __launch_bounds__(128) void nt64_tf32(
    const float* __restrict__ A, const float* __restrict__ B, float* __restrict__ C,
    int K, int lda, int ldb, int ldc)
{
    __shared__ float As[64][36];
    __shared__ float Bs[64][36];

    int tid = threadIdx.x;
    int lane = tid & 31;
    int warp = tid >> 5;
    int wm = warp >> 1;
    int wn = warp & 1;
    int tm = blockIdx.y * 64, tn = blockIdx.x * 64;

    float acc[2][4][4];
#pragma unroll
    for (int mt = 0; mt < 2; mt++)
#pragma unroll
        for (int nt = 0; nt < 4; nt++)
#pragma unroll
            for (int q = 0; q < 4; q++) acc[mt][nt][q] = 0.0f;

    int g = lane >> 2;
    int t4 = lane & 3;

    for (int k0 = 0; k0 < K; k0 += 32) {
        // A: 64x32 = 512 float4, 4/thread; B same
#pragma unroll
        for (int f = tid; f < 512; f += 128) {
            int row = f >> 3, c = (f & 7) << 2;
            float4 v = *reinterpret_cast<const float4*>(A + (size_t)(tm + row) * lda + k0 + c);
            As[row][c + 0] = __uint_as_float(f2tf32(v.x));
            As[row][c + 1] = __uint_as_float(f2tf32(v.y));
            As[row][c + 2] = __uint_as_float(f2tf32(v.z));
            As[row][c + 3] = __uint_as_float(f2tf32(v.w));
        }
#pragma unroll
        for (int f = tid; f < 512; f += 128) {
            int row = f >> 3, c = (f & 7) << 2;
            float4 v = *reinterpret_cast<const float4*>(B + (size_t)(tn + row) * ldb + k0 + c);
            Bs[row][c + 0] = __uint_as_float(f2tf32(v.x));
            Bs[row][c + 1] = __uint_as_float(f2tf32(v.y));
            Bs[row][c + 2] = __uint_as_float(f2tf32(v.z));
            Bs[row][c + 3] = __uint_as_float(f2tf32(v.w));
        }
        __syncthreads();

#pragma unroll
        for (int ks = 0; ks < 32; ks += 8) {
            int kc = ks + t4;
            uint32_t a[2][4], b[4][2];
#pragma unroll
            for (int mt = 0; mt < 2; mt++) {
                int r = wm * 32 + mt * 16 + g;
                a[mt][0] = __float_as_uint(As[r][kc]);
                a[mt][1] = __float_as_uint(As[r + 8][kc]);
                a[mt][2] = __float_as_uint(As[r][kc + 4]);
                a[mt][3] = __float_as_uint(As[r + 8][kc + 4]);
            }
#pragma unroll
            for (int nt = 0; nt < 4; nt++) {
                int n = wn * 32 + nt * 8 + g;
                b[nt][0] = __float_as_uint(Bs[n][kc]);
                b[nt][1] = __float_as_uint(Bs[n][kc + 4]);
            }
#pragma unroll
            for (int mt = 0; mt < 2; mt++)
#pragma unroll
                for (int nt = 0; nt < 4; nt++)
                    mma_tf32(acc[mt][nt][0], acc[mt][nt][1], acc[mt][nt][2], acc[mt][nt][3],
                             a[mt][0], a[mt][1], a[mt][2], a[mt][3], b[nt][0], b[nt][1]);
        }
        __syncthreads();
    }

#pragma unroll
    for (int mt = 0; mt < 2; mt++) {
        int row = tm + wm * 32 + mt * 16 + g;
#pragma unroll
        for (int nt = 0; nt < 4; nt++) {
            int col = tn + wn * 32 + nt * 8 + t4 * 2;
            *reinterpret_cast<float2*>(C + (size_t)row * ldc + col) =
                make_float2(acc[mt][nt][0], acc[mt][nt][1]);
            *reinterpret_cast<float2*>(C + (size_t)(row + 8) * ldc + col) =
                make_float2(acc[mt][nt][2], acc[mt][nt][3]);
        }
    }
}

// ---------------------------------------------------------------------------
// TF32 NN GEMM, 32x64 tile, 64 threads (2 warps of 32x32) — attn@V (512 CTAs).
// ---------------------------------------------------------------------------
__global__ __launch_bounds__(64) void nn32_tf32(
    const float* __restrict__ A, const float* __restrict__ B, float* __restrict__ C,
    int K, int lda, int ldb, int ldc,
    int inner, size_t aOut, size_t aIn, size_t bOut, size_t bIn, size_t cOut, size_t cIn)
{
    int z = blockIdx.z;
    int zo = z / inner, zi = z - zo * inner;
    A += zo * aOut + zi * aIn;
    B += zo * bOut + zi * bIn;
    C += zo * cOut + zi * cIn;

    __shared__ float As[32][20];
    __shared__ float Bs[64][20];

    int tid = threadIdx.x;
    int lane = tid & 31;
    int wn = tid >> 5;              // warp 0 or 1 -> n half
    int tm = blockIdx.y * 32, tn = blockIdx.x * 64;

    float acc[2][4][4];
#pragma unroll
    for (int mt = 0; mt < 2; mt++)
#pragma unroll
        for (int nt = 0; nt < 4; nt++)
#pragma unroll
            for (int q = 0; q < 4; q++) acc[mt][nt][q] = 0.0f;

    int g = lane >> 2;
    int t4 = lane & 3;

    for (int k0 = 0; k0 < K; k0 += 16) {
        // A: 32x16 = 128 float4, 2/thread
#pragma unroll
        for (int f = tid; f < 128; f += 64) {
            int row = f >> 2, c = (f & 3) << 2;
            float4 v = *reinterpret_cast<const float4*>(A + (size_t)(tm + row) * lda + k0 + c);
            As[row][c + 0] = __uint_as_float(f2tf32(v.x));
            As[row][c + 1] = __uint_as_float(f2tf32(v.y));
            As[row][c + 2] = __uint_as_float(f2tf32(v.z));
            As[row][c + 3] = __uint_as_float(f2tf32(v.w));
        }
        // B: 16k x 64n (n contiguous) -> transpose into Bs[n][k]; 256 float4, 4/thread
#pragma unroll
        for (int f = tid; f < 256; f += 64) {
            int kr = f >> 4, n4 = (f & 15) << 2;
            float4 v = *reinterpret_cast<const float4*>(B + (size_t)(k0 + kr) * ldb + tn + n4);
            Bs[n4 + 0][kr] = __uint_as_float(f2tf32(v.x));
            Bs[n4 + 1][kr] = __uint_as_float(f2tf32(v.y));
            Bs[n4 + 2][kr] = __uint_as_float(f2tf32(v.z));
            Bs[n4 + 3][kr] = __uint_as_float(f2tf32(v.w));
        }
        __syncthreads();

#pragma unroll
        for (int ks = 0; ks < 16; ks += 8) {
            int kc = ks + t4;
            uint32_t a[2][4], b[4][2];
#pragma unroll
            for (int mt = 0; mt < 2; mt++) {
                int r = mt * 16 + g;
                a[mt][0] = __float_as_uint(As[r][kc]);
                a[mt][1] = __float_as_uint(As[r + 8][kc]);
                a[mt][2] = __float_as_uint(As[r][kc + 4]);
                a[mt][3] = __float_as_uint(As[r + 8][kc + 4]);
            }
#pragma unroll
            for (int nt = 0; nt < 4; nt++) {
                int n = wn * 32 + nt * 8 + g;
                b[nt][0] = __float_as_uint(Bs[n][kc]);
                b[nt][1] = __float_as_uint(Bs[n][kc + 4]);
            }
#pragma unroll
            for (int mt = 0; mt < 2; mt++)
#pragma unroll
                for (int nt = 0; nt < 4; nt++)
                    mma_tf32(acc[mt][nt][0], acc[mt][nt][1], acc[mt][nt][2], acc[mt][nt][3],
                             a[mt][0], a[mt][1], a[mt][2], a[mt][3], b[nt][0], b[nt][1]);
        }
        __syncthreads();
    }

#pragma unroll
    for (int mt = 0; mt < 2; mt++) {
        int row = tm + mt * 16 + g;
#pragma unroll
        for (int nt = 0; nt < 4; nt++) {
            int col = tn + wn * 32 + nt * 8 + t4 * 2;
            *reinterpret_cast<float2*>(C + (size_t)row * ldc + col) =
                make_float2(acc[mt][nt][0], acc[mt][nt][1]);
            *reinterpret_cast<float2*>(C + (size_t)(row + 8) * ldc + col) =
                make_float2(acc[mt][nt][2], acc[mt][nt][3]);
        }
    }
}

// ---------------------------------------------------------------------------
// Mix MLP — scalar FFMA, float4 weight loads (proven 91.6us body).
// ---------------------------------------------------------------------------
__global__ __launch_bounds__(128) void mix_kernel(
    const float* __restrict__ cost, const float* __restrict__ W1,
    const float* __restrict__ W2, float* __restrict__ logits)
{
    __shared__ __align__(16) float4 w1e4[128][2];
    __shared__ __align__(16) float4 w2s4[128][2];
    __shared__ float w1o[128];

    int tx = threadIdx.x;
    {
        float s = 0.0f;
        float e[8];
#pragma unroll
        for (int h = 0; h < 8; h++) {
            e[h] = W1[tx * 16 + 2 * h];
            s += W1[tx * 16 + 2 * h + 1];
        }
        w1e4[tx][0] = make_float4(e[0], e[1], e[2], e[3]);
        w1e4[tx][1] = make_float4(e[4], e[5], e[6], e[7]);
        w1o[tx] = s;
        float t[8];
#pragma unroll
        for (int j = 0; j < 8; j++) t[j] = W2[j * 128 + tx];
        w2s4[tx][0] = make_float4(t[0], t[1], t[2], t[3]);
        w2s4[tx][1] = make_float4(t[4], t[5], t[6], t[7]);
    }
    __syncthreads();

    int br = blockIdx.x;
    int b = br >> 9;
    int r = br & 511;
    int c0 = tx * 4;

    float dv[8][4];
#pragma unroll
    for (int h = 0; h < 8; h++) {
        float4 t = *reinterpret_cast<const float4*>(
            logits + (((size_t)(b * NH + h) * NR + r) * NC + c0));
        dv[h][0] = t.x; dv[h][1] = t.y; dv[h][2] = t.z; dv[h][3] = t.w;
    }
    float4 cvv = *reinterpret_cast<const float4*>(cost + ((size_t)b * NR + r) * NC + c0);
    float cw[4] = {cvv.x, cvv.y, cvv.z, cvv.w};

    float ms[4][8];
#pragma unroll
    for (int p = 0; p < 4; p++)
#pragma unroll
        for (int h = 0; h < 8; h++) ms[p][h] = 0.0f;

#pragma unroll 2
    for (int i = 0; i < 128; i++) {
        float wo = w1o[i];
        float4 wa = w1e4[i][0];
        float4 wb = w1e4[i][1];

        float h0 = cw[0] * wo, h1 = cw[1] * wo, h2 = cw[2] * wo, h3 = cw[3] * wo;
        h0 = fmaf(dv[0][0], wa.x, h0); h1 = fmaf(dv[0][1], wa.x, h1); h2 = fmaf(dv[0][2], wa.x, h2); h3 = fmaf(dv[0][3], wa.x, h3);
        h0 = fmaf(dv[1][0], wa.y, h0); h1 = fmaf(dv[1][1], wa.y, h1); h2 = fmaf(dv[1][2], wa.y, h2); h3 = fmaf(dv[1][3], wa.y, h3);
        h0 = fmaf(dv[2][0], wa.z, h0); h1 = fmaf(dv[2][1], wa.z, h1); h2 = fmaf(dv[2][2], wa.z, h2); h3 = fmaf(dv[2][3], wa.z, h3);
        h0 = fmaf(dv[3][0], wa.w, h0); h1 = fmaf(dv[3][1], wa.w, h1); h2 = fmaf(dv[3][2], wa.w, h2); h3 = fmaf(dv[3][3], wa.w, h3);
        h0 = fmaf(dv[4][0], wb.x, h0); h1 = fmaf(dv[4][1], wb.x, h1); h2 = fmaf(dv[4][2], wb.x, h2); h3 = fmaf(dv[4][3], wb.x, h3);
        h0 = fmaf(dv[5][0], wb.y, h0); h1 = fmaf(dv[5][1], wb.y, h1); h2 = fmaf(dv[5][2], wb.y, h2); h3 = fmaf(dv[5][3], wb.y, h3);
        h0 = fmaf(dv[6][0], wb.z, h0); h1 = fmaf(dv[6][1], wb.z, h1); h2 = fmaf(dv[6][2], wb.z, h2); h3 = fmaf(dv[6][3], wb.z, h3);
        h0 = fmaf(dv[7][0], wb.w, h0); h1 = fmaf(dv[7][1], wb.w, h1); h2 = fmaf(dv[7][2], wb.w, h2); h3 = fmaf(dv[7][3], wb.w, h3);

        h0 = fmaxf(h0, 0.0f); h1 = fmaxf(h1, 0.0f); h2 = fmaxf(h2, 0.0f); h3 = fmaxf(h3, 0.0f);

        float4 va = w2s4[i][0];
        float4 vb = w2s4[i][1];
        ms[0][0] = fmaf(h0, va.x, ms[0][0]); ms[1][0] = fmaf(h1, va.x, ms[1][0]); ms[2][0] = fmaf(h2, va.x, ms[2][0]); ms[3][0] = fmaf(h3, va.x, ms[3][0]);
        ms[0][1] = fmaf(h0, va.y, ms[0][1]); ms[1][1] = fmaf(h1, va.y, ms[1][1]); ms[2][1] = fmaf(h2, va.y, ms[2][1]); ms[3][1] = fmaf(h3, va.y, ms[3][1]);
        ms[0][2] = fmaf(h0, va.z, ms[0][2]); ms[1][2] = fmaf(h1, va.z, ms[1][2]); ms[2][2] = fmaf(h2, va.z, ms[2][2]); ms[3][2] = fmaf(h3, va.z, ms[3][2]);
        ms[0][3] = fmaf(h0, va.w, ms[0][3]); ms[1][3] = fmaf(h1, va.w, ms[1][3]); ms[2][3] = fmaf(h2, va.w, ms[2][3]); ms[3][3] = fmaf(h3, va.w, ms[3][3]);
        ms[0][4] = fmaf(h0, vb.x, ms[0][4]); ms[1][4] = fmaf(h1, vb.x, ms[1][4]); ms[2][4] = fmaf(h2, vb.x, ms[2][4]); ms[3][4] = fmaf(h3, vb.x, ms[3][4]);
        ms[0][5] = fmaf(h0, vb.y, ms[0][5]); ms[1][5] = fmaf(h1, vb.y, ms[1][5]); ms[2][5] = fmaf(h2, vb.y, ms[2][5]); ms[3][5] = fmaf(h3, vb.y, ms[3][5]);
        ms[0][6] = fmaf(h0, vb.z, ms[0][6]); ms[1][6] = fmaf(h1, vb.z, ms[1][6]); ms[2][6] = fmaf(h2, vb.z, ms[2][6]); ms[3][6] = fmaf(h3, vb.z, ms[3][6]);
        ms[0][7] = fmaf(h0, vb.w, ms[0][7]); ms[1][7] = fmaf(h1, vb.w, ms[1][7]); ms[2][7] = fmaf(h2, vb.w, ms[2][7]); ms[3][7] = fmaf(h3, vb.w, ms[3][7]);
    }

#pragma unroll
    for (int h = 0; h < 8; h++) {
        float4 o = make_float4(ms[0][h], ms[1][h], ms[2][h], ms[3][h]);
        *reinterpret_cast<float4*>(logits + (((size_t)(b * NH + h) * NR + r) * NC + c0)) = o;
    }
}

// ---------------------------------------------------------------------------
// Masked softmax (exact Round-3 body). Fully-masked rows become unmasked.
// ---------------------------------------------------------------------------
__global__ __launch_bounds__(128) void softmax_kernel(
    float* __restrict__ logits, const void* __restrict__ maskv)
{
    int row = blockIdx.x;
    float* lg = logits + (size_t)row * NC;
    int tx = threadIdx.x;
    int lane = tx & 31, wid = tx >> 5;

    float4 v = reinterpret_cast<const float4*>(lg)[tx];

    uchar4 mk;
    if (g_mask_is_i32) {
        int4 t = reinterpret_cast<const int4*>(maskv)[(size_t)row * (NC / 4) + tx];
        mk = make_uchar4(t.x != 0, t.y != 0, t.z != 0, t.w != 0);
    } else {
        mk = reinterpret_cast<const uchar4*>(maskv)[(size_t)row * (NC / 4) + tx];
    }

    __shared__ float pmax[4];
    __shared__ float psum[4];
    __shared__ int pall[4];

    bool mine_all = (mk.x != 0) && (mk.y != 0) && (mk.z != 0) && (mk.w != 0);
    unsigned bal = __ballot_sync(0xffffffffu, mine_all);
    if (lane == 0) pall[wid] = (bal == 0xffffffffu) ? 1 : 0;
    __syncthreads();
    bool am = pall[0] && pall[1] && pall[2] && pall[3];

    const float NEG = __int_as_float(0xff800000);  // -inf
    float x0 = (!am && mk.x) ? NEG : v.x;
    float x1 = (!am && mk.y) ? NEG : v.y;
    float x2 = (!am && mk.z) ? NEG : v.z;
    float x3 = (!am && mk.w) ? NEG : v.w;

    float m = fmaxf(fmaxf(x0, x1), fmaxf(x2, x3));
#pragma unroll
    for (int s = 16; s > 0; s >>= 1) m = fmaxf(m, __shfl_xor_sync(0xffffffffu, m, s));
    if (lane == 0) pmax[wid] = m;
    __syncthreads();
    float rmax = fmaxf(fmaxf(pmax[0], pmax[1]), fmaxf(pmax[2], pmax[3]));

    float e0 = __expf(x0 - rmax);
    float e1 = __expf(x1 - rmax);
    float e2 = __expf(x2 - rmax);
    float e3 = __expf(x3 - rmax);

    float sm = (e0 + e1) + (e2 + e3);
#pragma unroll
    for (int s = 16; s > 0; s >>= 1) sm += __shfl_xor_sync(0xffffffffu, sm, s);
    if (lane == 0) psum[wid] = sm;
    __syncthreads();
    float inv = 1.0f / (((psum[0] + psum[1]) + (psum[2] + psum[3])));

    float4 o = make_float4(e0 * inv, e1 * inv, e2 * inv, e3 * inv);
    reinterpret_cast<float4*>(lg)[tx] = o;
}

// ---------------------------------------------------------------------------
extern "C" void kernel_launch(void* const* d_in, const int* in_sizes, int n_in,
                              void* d_out, int out_size)
{
    const float* row_emb = (const float*)d_in[0];
    const float* col_emb = (const float*)d_in[1];
    const float* cost    = (const float*)d_in[2];
    const void*  mask    = d_in[3];
    const float* Wq      = (const float*)d_in[4];
    const float* Wk      = (const float*)d_in[5];
    const float* Wv      = (const float*)d_in[6];
    const float* Wmix1   = (const float*)d_in[7];
    const float* Wmix2   = (const float*)d_in[8];
    const float* Wout    = (const float*)d_in[9];
    float* out = (float*)d_out;

    float *Q, *K, *V, *L, *AT;
    cudaGetSymbolAddress((void**)&Q,  g_Q);
    cudaGetSymbolAddress((void**)&K,  g_K);
    cudaGetSymbolAddress((void**)&V,  g_V);
    cudaGetSymbolAddress((void**)&L,  g_logits);
    cudaGetSymbolAddress((void**)&AT, g_attn);

    const size_t RE = (size_t)NR * NE;      // 262144
    const size_t RC = (size_t)NR * NC;      // 262144

    detect_mask_kernel<<<1, 1>>>((const unsigned char*)mask);

    // Q/K/V projections — TF32, K-tile 32 (384 CTAs)
    qkv_gemm_tf32<<<dim3(NE / 64, (NB * NR) / 128, 3), 256>>>(
        row_emb, col_emb, Wq, Wk, Wv, Q, K, V);

    // dot[b,h,r,c] = (1/8) * q . k — TF32 NT (1024 CTAs)
    nt_tf32<<<dim3(NC / 64, NR / 128, NB * NH), 256>>>(
        Q, K, L, ND, NE, NE, NC,
        NH, RE, (size_t)ND, RE, (size_t)ND, (size_t)NH * RC, RC,
        0.125f);

    // mix MLP — scalar (2048 CTAs), in place on L
    mix_kernel<<<NB * NR, 128>>>(cost, Wmix1, Wmix2, L);

    // masked softmax (in place on L)
    softmax_kernel<<<NB * NH * NR, 128>>>(L, mask);

    // attn @ V — TF32 NN, 32x64 tiles (512 CTAs)
    nn32_tf32<<<dim3(1, NR / 32, NB * NH), 64>>>(
        L, V, AT, NC, NC, NE, NE,
        NH, (size_t)NH * RC, RC, (size_t)NC * NE, (size_t)ND, RE, (size_t)ND);

    // final projection — TF32 NT, 64x64 tiles (256 CTAs)
    nt64_tf32<<<dim3(NE / 64, (NB * NR) / 64), 128>>>(
        AT, Wout, out, NE, NE, NE, NE);
}

// round 17
// speedup vs baseline: 1.0341x; 1.0341x over previous
#include <cuda_runtime.h>
#include <cstdint>
#include <cstddef>

// Problem constants
#define NB 4
#define NH 8
#define ND 64
#define NE 512
#define NR 512
#define NC 512

// Scratch (device globals; allocation inside kernel_launch is forbidden)
__device__ float g_Q[NB * NR * NE];
__device__ float g_K[NB * NC * NE];
__device__ float g_V[NB * NC * NE];
__device__ float g_logits[(size_t)NB * NH * NR * NC];  // dot -> logits -> weights (in place)
__device__ float g_attn[NB * NR * NE];
__device__ int   g_mask_is_i32;

__device__ __forceinline__ uint32_t f2tf32(float x) {
    uint32_t u;
    asm("cvt.rna.tf32.f32 %0, %1;" : "=r"(u) : "f"(x));
    return u;
}

__device__ __forceinline__ void mma_tf32(
    float& c0, float& c1, float& c2, float& c3,
    uint32_t a0, uint32_t a1, uint32_t a2, uint32_t a3,
    uint32_t b0, uint32_t b1)
{
    asm volatile(
        "mma.sync.aligned.m16n8k8.row.col.f32.tf32.tf32.f32 "
        "{%0,%1,%2,%3}, {%4,%5,%6,%7}, {%8,%9}, {%0,%1,%2,%3};"
        : "+f"(c0), "+f"(c1), "+f"(c2), "+f"(c3)
        : "r"(a0), "r"(a1), "r"(a2), "r"(a3), "r"(b0), "r"(b1));
}

// ---------------------------------------------------------------------------
// Probe mask dtype (bool-as-int32 vs uint8). Reads 256 bytes.
// ---------------------------------------------------------------------------
__global__ void detect_mask_kernel(const unsigned char* __restrict__ m)
{
    int is32 = 1;
    for (int i = 0; i < 256; i++)
        if ((i & 3) != 0 && m[i] != 0) { is32 = 0; break; }
    g_mask_is_i32 = is32;
}

// ---------------------------------------------------------------------------
// Fused Q/K/V projection — TF32 mma, K-tile 32 (Round-15 winner, unchanged).
// ---------------------------------------------------------------------------
__global__ __launch_bounds__(256) void qkv_gemm_tf32(
    const float* __restrict__ row_emb, const float* __restrict__ col_emb,
    const float* __restrict__ Wq, const float* __restrict__ Wk, const float* __restrict__ Wv,
    float* __restrict__ Qo, float* __restrict__ Ko, float* __restrict__ Vo)
{
    int z = blockIdx.z;
    const float* A = (z == 0) ? row_emb : col_emb;
    const float* B = (z == 0) ? Wq : (z == 1) ? Wk : Wv;
    float* C = (z == 0) ? Qo : (z == 1) ? Ko : Vo;

    __shared__ float As[128][36];
    __shared__ float Bs[64][36];

    int tid = threadIdx.x;
    int lane = tid & 31;
    int warp = tid >> 5;
    int wm = warp >> 1;
    int wn = warp & 1;
    int tm = blockIdx.y * 128, tn = blockIdx.x * 64;

    float acc[2][4][4];
#pragma unroll
    for (int mt = 0; mt < 2; mt++)
#pragma unroll
        for (int nt = 0; nt < 4; nt++)
#pragma unroll
            for (int q = 0; q < 4; q++) acc[mt][nt][q] = 0.0f;

    int g = lane >> 2;
    int t4 = lane & 3;

    for (int k0 = 0; k0 < NE; k0 += 32) {
#pragma unroll
        for (int f = tid; f < 1024; f += 256) {
            int row = f >> 3, c = (f & 7) << 2;
            float4 v = *reinterpret_cast<const float4*>(A + (size_t)(tm + row) * NE + k0 + c);
            As[row][c + 0] = __uint_as_float(f2tf32(v.x));
            As[row][c + 1] = __uint_as_float(f2tf32(v.y));
            As[row][c + 2] = __uint_as_float(f2tf32(v.z));
            As[row][c + 3] = __uint_as_float(f2tf32(v.w));
        }
#pragma unroll
        for (int f = tid; f < 512; f += 256) {
            int row = f >> 3, c = (f & 7) << 2;
            float4 v = *reinterpret_cast<const float4*>(B + (size_t)(tn + row) * NE + k0 + c);
            Bs[row][c + 0] = __uint_as_float(f2tf32(v.x));
            Bs[row][c + 1] = __uint_as_float(f2tf32(v.y));
            Bs[row][c + 2] = __uint_as_float(f2tf32(v.z));
            Bs[row][c + 3] = __uint_as_float(f2tf32(v.w));
        }
        __syncthreads();

#pragma unroll
        for (int ks = 0; ks < 32; ks += 8) {
            int kc = ks + t4;
            uint32_t a[2][4], b[4][2];
#pragma unroll
            for (int mt = 0; mt < 2; mt++) {
                int r = wm * 32 + mt * 16 + g;
                a[mt][0] = __float_as_uint(As[r][kc]);
                a[mt][1] = __float_as_uint(As[r + 8][kc]);
                a[mt][2] = __float_as_uint(As[r][kc + 4]);
                a[mt][3] = __float_as_uint(As[r + 8][kc + 4]);
            }
#pragma unroll
            for (int nt = 0; nt < 4; nt++) {
                int n = wn * 32 + nt * 8 + g;
                b[nt][0] = __float_as_uint(Bs[n][kc]);
                b[nt][1] = __float_as_uint(Bs[n][kc + 4]);
            }
#pragma unroll
            for (int mt = 0; mt < 2; mt++)
#pragma unroll
                for (int nt = 0; nt < 4; nt++)
                    mma_tf32(acc[mt][nt][0], acc[mt][nt][1], acc[mt][nt][2], acc[mt][nt][3],
                             a[mt][0], a[mt][1], a[mt][2], a[mt][3], b[nt][0], b[nt][1]);
        }
        __syncthreads();
    }

#pragma unroll
    for (int mt = 0; mt < 2; mt++) {
        int row = tm + wm * 32 + mt * 16 + g;
#pragma unroll
        for (int nt = 0; nt < 4; nt++) {
            int col = tn + wn * 32 + nt * 8 + t4 * 2;
            *reinterpret_cast<float2*>(C + (size_t)row * NE + col) =
                make_float2(acc[mt][nt][0], acc[mt][nt][1]);
            *reinterpret_cast<float2*>(C + (size_t)(row + 8) * NE + col) =
                make_float2(acc[mt][nt][2], acc[mt][nt][3]);
        }
    }
}

// ---------------------------------------------------------------------------
// Generic TF32 NT GEMM, K-tile 32, 128x64 tile (Round-15 winner). qk^T.
// ---------------------------------------------------------------------------
__global__ __launch_bounds__(256) void nt_tf32(
    const float* __restrict__ A, const float* __restrict__ B, float* __restrict__ C,
    int K, int lda, int ldb, int ldc,
    int inner, size_t aOut, size_t aIn, size_t bOut, size_t bIn, size_t cOut, size_t cIn,
    float alpha)
{
    int z = blockIdx.z;
    int zo = z / inner, zi = z - zo * inner;
    A += zo * aOut + zi * aIn;
    B += zo * bOut + zi * bIn;
    C += zo * cOut + zi * cIn;

    __shared__ float As[128][36];
    __shared__ float Bs[64][36];

    int tid = threadIdx.x;
    int lane = tid & 31;
    int warp = tid >> 5;
    int wm = warp >> 1;
    int wn = warp & 1;
    int tm = blockIdx.y * 128, tn = blockIdx.x * 64;

    float acc[2][4][4];
#pragma unroll
    for (int mt = 0; mt < 2; mt++)
#pragma unroll
        for (int nt = 0; nt < 4; nt++)
#pragma unroll
            for (int q = 0; q < 4; q++) acc[mt][nt][q] = 0.0f;

    int g = lane >> 2;
    int t4 = lane & 3;

    for (int k0 = 0; k0 < K; k0 += 32) {
#pragma unroll
        for (int f = tid; f < 1024; f += 256) {
            int row = f >> 3, c = (f & 7) << 2;
            float4 v = *reinterpret_cast<const float4*>(A + (size_t)(tm + row) * lda + k0 + c);
            As[row][c + 0] = __uint_as_float(f2tf32(v.x));
            As[row][c + 1] = __uint_as_float(f2tf32(v.y));
            As[row][c + 2] = __uint_as_float(f2tf32(v.z));
            As[row][c + 3] = __uint_as_float(f2tf32(v.w));
        }
#pragma unroll
        for (int f = tid; f < 512; f += 256) {
            int row = f >> 3, c = (f & 7) << 2;
            float4 v = *reinterpret_cast<const float4*>(B + (size_t)(tn + row) * ldb + k0 + c);
            Bs[row][c + 0] = __uint_as_float(f2tf32(v.x));
            Bs[row][c + 1] = __uint_as_float(f2tf32(v.y));
            Bs[row][c + 2] = __uint_as_float(f2tf32(v.z));
            Bs[row][c + 3] = __uint_as_float(f2tf32(v.w));
        }
        __syncthreads();

#pragma unroll
        for (int ks = 0; ks < 32; ks += 8) {
            int kc = ks + t4;
            uint32_t a[2][4], b[4][2];
#pragma unroll
            for (int mt = 0; mt < 2; mt++) {
                int r = wm * 32 + mt * 16 + g;
                a[mt][0] = __float_as_uint(As[r][kc]);
                a[mt][1] = __float_as_uint(As[r + 8][kc]);
                a[mt][2] = __float_as_uint(As[r][kc + 4]);
                a[mt][3] = __float_as_uint(As[r + 8][kc + 4]);
            }
#pragma unroll
            for (int nt = 0; nt < 4; nt++) {
                int n = wn * 32 + nt * 8 + g;
                b[nt][0] = __float_as_uint(Bs[n][kc]);
                b[nt][1] = __float_as_uint(Bs[n][kc + 4]);
            }
#pragma unroll
            for (int mt = 0; mt < 2; mt++)
#pragma unroll
                for (int nt = 0; nt < 4; nt++)
                    mma_tf32(acc[mt][nt][0], acc[mt][nt][1], acc[mt][nt][2], acc[mt][nt][3],
                             a[mt][0], a[mt][1], a[mt][2], a[mt][3], b[nt][0], b[nt][1]);
        }
        __syncthreads();
    }

#pragma unroll
    for (int mt = 0; mt < 2; mt++) {
        int row = tm + wm * 32 + mt * 16 + g;
#pragma unroll
        for (int nt = 0; nt < 4; nt++) {
            int col = tn + wn * 32 + nt * 8 + t4 * 2;
            *reinterpret_cast<float2*>(C + (size_t)row * ldc + col) =
                make_float2(alpha * acc[mt][nt][0], alpha * acc[mt][nt][1]);
            *reinterpret_cast<float2*>(C + (size_t)(row + 8) * ldc + col) =
                make_float2(alpha * acc[mt][nt][2], alpha * acc[mt][nt][3]);
        }
    }
}

// ---------------------------------------------------------------------------
// TF32 NT GEMM, 64x64 tile, 128 threads, K-tile 32 — outproj (256 CTAs).
// Same 32x32 warp math as nt_tf32 -> bit-identical numerics.
// ---------------------------------------------------------------------------
__global__ __launch_bounds__(128) void nt64_tf32(
    const float* __restrict__ A, const float* __restrict__ B, float* __restrict__ C,
    int K, int lda, int ldb, int ldc)
{
    __shared__ float As[64][36];
    __shared__ float Bs[64][36];

    int tid = threadIdx.x;
    int lane = tid & 31;
    int warp = tid >> 5;
    int wm = warp >> 1;
    int wn = warp & 1;
    int tm = blockIdx.y * 64, tn = blockIdx.x * 64;

    float acc[2][4][4];
#pragma unroll
    for (int mt = 0; mt < 2; mt++)
#pragma unroll
        for (int nt = 0; nt < 4; nt++)
#pragma unroll
            for (int q = 0; q < 4; q++) acc[mt][nt][q] = 0.0f;

    int g = lane >> 2;
    int t4 = lane & 3;

    for (int k0 = 0; k0 < K; k0 += 32) {
#pragma unroll
        for (int f = tid; f < 512; f += 128) {
            int row = f >> 3, c = (f & 7) << 2;
            float4 v = *reinterpret_cast<const float4*>(A + (size_t)(tm + row) * lda + k0 + c);
            As[row][c + 0] = __uint_as_float(f2tf32(v.x));
            As[row][c + 1] = __uint_as_float(f2tf32(v.y));
            As[row][c + 2] = __uint_as_float(f2tf32(v.z));
            As[row][c + 3] = __uint_as_float(f2tf32(v.w));
        }
#pragma unroll
        for (int f = tid; f < 512; f += 128) {
            int row = f >> 3, c = (f & 7) << 2;
            float4 v = *reinterpret_cast<const float4*>(B + (size_t)(tn + row) * ldb + k0 + c);
            Bs[row][c + 0] = __uint_as_float(f2tf32(v.x));
            Bs[row][c + 1] = __uint_as_float(f2tf32(v.y));
            Bs[row][c + 2] = __uint_as_float(f2tf32(v.z));
            Bs[row][c + 3] = __uint_as_float(f2tf32(v.w));
        }
        __syncthreads();

#pragma unroll
        for (int ks = 0; ks < 32; ks += 8) {
            int kc = ks + t4;
            uint32_t a[2][4], b[4][2];
#pragma unroll
            for (int mt = 0; mt < 2; mt++) {
                int r = wm * 32 + mt * 16 + g;
                a[mt][0] = __float_as_uint(As[r][kc]);
                a[mt][1] = __float_as_uint(As[r + 8][kc]);
                a[mt][2] = __float_as_uint(As[r][kc + 4]);
                a[mt][3] = __float_as_uint(As[r + 8][kc + 4]);
            }
#pragma unroll
            for (int nt = 0; nt < 4; nt++) {
                int n = wn * 32 + nt * 8 + g;
                b[nt][0] = __float_as_uint(Bs[n][kc]);
                b[nt][1] = __float_as_uint(Bs[n][kc + 4]);
            }
#pragma unroll
            for (int mt = 0; mt < 2; mt++)
#pragma unroll
                for (int nt = 0; nt < 4; nt++)
                    mma_tf32(acc[mt][nt][0], acc[mt][nt][1], acc[mt][nt][2], acc[mt][nt][3],
                             a[mt][0], a[mt][1], a[mt][2], a[mt][3], b[nt][0], b[nt][1]);
        }
        __syncthreads();
    }

#pragma unroll
    for (int mt = 0; mt < 2; mt++) {
        int row = tm + wm * 32 + mt * 16 + g;
#pragma unroll
        for (int nt = 0; nt < 4; nt++) {
            int col = tn + wn * 32 + nt * 8 + t4 * 2;
            *reinterpret_cast<float2*>(C + (size_t)row * ldc + col) =
                make_float2(acc[mt][nt][0], acc[mt][nt][1]);
            *reinterpret_cast<float2*>(C + (size_t)(row + 8) * ldc + col) =
                make_float2(acc[mt][nt][2], acc[mt][nt][3]);
        }
    }
}

// ---------------------------------------------------------------------------
// TF32 NN GEMM (Round-11 winner, unchanged). attn @ V.
// ---------------------------------------------------------------------------
__global__ __launch_bounds__(128) void nn_tf32(
    const float* __restrict__ A, const float* __restrict__ B, float* __restrict__ C,
    int K, int lda, int ldb, int ldc,
    int inner, size_t aOut, size_t aIn, size_t bOut, size_t bIn, size_t cOut, size_t cIn)
{
    int z = blockIdx.z;
    int zo = z / inner, zi = z - zo * inner;
    A += zo * aOut + zi * aIn;
    B += zo * bOut + zi * bIn;
    C += zo * cOut + zi * cIn;

    __shared__ float As[64][20];
    __shared__ float Bs[64][20];

    int tid = threadIdx.x;
    int lane = tid & 31;
    int warp = tid >> 5;
    int wm = warp >> 1;
    int wn = warp & 1;
    int tm = blockIdx.y * 64, tn = blockIdx.x * 64;

    float acc[2][4][4];
#pragma unroll
    for (int mt = 0; mt < 2; mt++)
#pragma unroll
        for (int nt = 0; nt < 4; nt++)
#pragma unroll
            for (int q = 0; q < 4; q++) acc[mt][nt][q] = 0.0f;

    int g = lane >> 2;
    int t4 = lane & 3;

    for (int k0 = 0; k0 < K; k0 += 16) {
#pragma unroll
        for (int f = tid; f < 256; f += 128) {
            int row = f >> 2, c = (f & 3) << 2;
            float4 v = *reinterpret_cast<const float4*>(A + (size_t)(tm + row) * lda + k0 + c);
            As[row][c + 0] = __uint_as_float(f2tf32(v.x));
            As[row][c + 1] = __uint_as_float(f2tf32(v.y));
            As[row][c + 2] = __uint_as_float(f2tf32(v.z));
            As[row][c + 3] = __uint_as_float(f2tf32(v.w));
        }
#pragma unroll
        for (int f = tid; f < 256; f += 128) {
            int kr = f >> 4, n4 = (f & 15) << 2;
            float4 v = *reinterpret_cast<const float4*>(B + (size_t)(k0 + kr) * ldb + tn + n4);
            Bs[n4 + 0][kr] = __uint_as_float(f2tf32(v.x));
            Bs[n4 + 1][kr] = __uint_as_float(f2tf32(v.y));
            Bs[n4 + 2][kr] = __uint_as_float(f2tf32(v.z));
            Bs[n4 + 3][kr] = __uint_as_float(f2tf32(v.w));
        }
        __syncthreads();

#pragma unroll
        for (int ks = 0; ks < 16; ks += 8) {
            int kc = ks + t4;
            uint32_t a[2][4], b[4][2];
#pragma unroll
            for (int mt = 0; mt < 2; mt++) {
                int r = wm * 32 + mt * 16 + g;
                a[mt][0] = __float_as_uint(As[r][kc]);
                a[mt][1] = __float_as_uint(As[r + 8][kc]);
                a[mt][2] = __float_as_uint(As[r][kc + 4]);
                a[mt][3] = __float_as_uint(As[r + 8][kc + 4]);
            }
#pragma unroll
            for (int nt = 0; nt < 4; nt++) {
                int n = wn * 32 + nt * 8 + g;
                b[nt][0] = __float_as_uint(Bs[n][kc]);
                b[nt][1] = __float_as_uint(Bs[n][kc + 4]);
            }
#pragma unroll
            for (int mt = 0; mt < 2; mt++)
#pragma unroll
                for (int nt = 0; nt < 4; nt++)
                    mma_tf32(acc[mt][nt][0], acc[mt][nt][1], acc[mt][nt][2], acc[mt][nt][3],
                             a[mt][0], a[mt][1], a[mt][2], a[mt][3], b[nt][0], b[nt][1]);
        }
        __syncthreads();
    }

#pragma unroll
    for (int mt = 0; mt < 2; mt++) {
        int row = tm + wm * 32 + mt * 16 + g;
#pragma unroll
        for (int nt = 0; nt < 4; nt++) {
            int col = tn + wn * 32 + nt * 8 + t4 * 2;
            *reinterpret_cast<float2*>(C + (size_t)row * ldc + col) =
                make_float2(acc[mt][nt][0], acc[mt][nt][1]);
            *reinterpret_cast<float2*>(C + (size_t)(row + 8) * ldc + col) =
                make_float2(acc[mt][nt][2], acc[mt][nt][3]);
        }
    }
}

// ---------------------------------------------------------------------------
// Mix MLP — scalar FFMA, float4 weight loads (proven 91.6us body).
// ---------------------------------------------------------------------------
__global__ __launch_bounds__(128) void mix_kernel(
    const float* __restrict__ cost, const float* __restrict__ W1,
    const float* __restrict__ W2, float* __restrict__ logits)
{
    __shared__ __align__(16) float4 w1e4[128][2];
    __shared__ __align__(16) float4 w2s4[128][2];
    __shared__ float w1o[128];

    int tx = threadIdx.x;
    {
        float s = 0.0f;
        float e[8];
#pragma unroll
        for (int h = 0; h < 8; h++) {
            e[h] = W1[tx * 16 + 2 * h];
            s += W1[tx * 16 + 2 * h + 1];
        }
        w1e4[tx][0] = make_float4(e[0], e[1], e[2], e[3]);
        w1e4[tx][1] = make_float4(e[4], e[5], e[6], e[7]);
        w1o[tx] = s;
        float t[8];
#pragma unroll
        for (int j = 0; j < 8; j++) t[j] = W2[j * 128 + tx];
        w2s4[tx][0] = make_float4(t[0], t[1], t[2], t[3]);
        w2s4[tx][1] = make_float4(t[4], t[5], t[6], t[7]);
    }
    __syncthreads();

    int br = blockIdx.x;
    int b = br >> 9;
    int r = br & 511;
    int c0 = tx * 4;

    float dv[8][4];
#pragma unroll
    for (int h = 0; h < 8; h++) {
        float4 t = *reinterpret_cast<const float4*>(
            logits + (((size_t)(b * NH + h) * NR + r) * NC + c0));
        dv[h][0] = t.x; dv[h][1] = t.y; dv[h][2] = t.z; dv[h][3] = t.w;
    }
    float4 cvv = *reinterpret_cast<const float4*>(cost + ((size_t)b * NR + r) * NC + c0);
    float cw[4] = {cvv.x, cvv.y, cvv.z, cvv.w};

    float ms[4][8];
#pragma unroll
    for (int p = 0; p < 4; p++)
#pragma unroll
        for (int h = 0; h < 8; h++) ms[p][h] = 0.0f;

#pragma unroll 2
    for (int i = 0; i < 128; i++) {
        float wo = w1o[i];
        float4 wa = w1e4[i][0];
        float4 wb = w1e4[i][1];

        float h0 = cw[0] * wo, h1 = cw[1] * wo, h2 = cw[2] * wo, h3 = cw[3] * wo;
        h0 = fmaf(dv[0][0], wa.x, h0); h1 = fmaf(dv[0][1], wa.x, h1); h2 = fmaf(dv[0][2], wa.x, h2); h3 = fmaf(dv[0][3], wa.x, h3);
        h0 = fmaf(dv[1][0], wa.y, h0); h1 = fmaf(dv[1][1], wa.y, h1); h2 = fmaf(dv[1][2], wa.y, h2); h3 = fmaf(dv[1][3], wa.y, h3);
        h0 = fmaf(dv[2][0], wa.z, h0); h1 = fmaf(dv[2][1], wa.z, h1); h2 = fmaf(dv[2][2], wa.z, h2); h3 = fmaf(dv[2][3], wa.z, h3);
        h0 = fmaf(dv[3][0], wa.w, h0); h1 = fmaf(dv[3][1], wa.w, h1); h2 = fmaf(dv[3][2], wa.w, h2); h3 = fmaf(dv[3][3], wa.w, h3);
        h0 = fmaf(dv[4][0], wb.x, h0); h1 = fmaf(dv[4][1], wb.x, h1); h2 = fmaf(dv[4][2], wb.x, h2); h3 = fmaf(dv[4][3], wb.x, h3);
        h0 = fmaf(dv[5][0], wb.y, h0); h1 = fmaf(dv[5][1], wb.y, h1); h2 = fmaf(dv[5][2], wb.y, h2); h3 = fmaf(dv[5][3], wb.y, h3);
        h0 = fmaf(dv[6][0], wb.z, h0); h1 = fmaf(dv[6][1], wb.z, h1); h2 = fmaf(dv[6][2], wb.z, h2); h3 = fmaf(dv[6][3], wb.z, h3);
        h0 = fmaf(dv[7][0], wb.w, h0); h1 = fmaf(dv[7][1], wb.w, h1); h2 = fmaf(dv[7][2], wb.w, h2); h3 = fmaf(dv[7][3], wb.w, h3);

        h0 = fmaxf(h0, 0.0f); h1 = fmaxf(h1, 0.0f); h2 = fmaxf(h2, 0.0f); h3 = fmaxf(h3, 0.0f);

        float4 va = w2s4[i][0];
        float4 vb = w2s4[i][1];
        ms[0][0] = fmaf(h0, va.x, ms[0][0]); ms[1][0] = fmaf(h1, va.x, ms[1][0]); ms[2][0] = fmaf(h2, va.x, ms[2][0]); ms[3][0] = fmaf(h3, va.x, ms[3][0]);
        ms[0][1] = fmaf(h0, va.y, ms[0][1]); ms[1][1] = fmaf(h1, va.y, ms[1][1]); ms[2][1] = fmaf(h2, va.y, ms[2][1]); ms[3][1] = fmaf(h3, va.y, ms[3][1]);
        ms[0][2] = fmaf(h0, va.z, ms[0][2]); ms[1][2] = fmaf(h1, va.z, ms[1][2]); ms[2][2] = fmaf(h2, va.z, ms[2][2]); ms[3][2] = fmaf(h3, va.z, ms[3][2]);
        ms[0][3] = fmaf(h0, va.w, ms[0][3]); ms[1][3] = fmaf(h1, va.w, ms[1][3]); ms[2][3] = fmaf(h2, va.w, ms[2][3]); ms[3][3] = fmaf(h3, va.w, ms[3][3]);
        ms[0][4] = fmaf(h0, vb.x, ms[0][4]); ms[1][4] = fmaf(h1, vb.x, ms[1][4]); ms[2][4] = fmaf(h2, vb.x, ms[2][4]); ms[3][4] = fmaf(h3, vb.x, ms[3][4]);
        ms[0][5] = fmaf(h0, vb.y, ms[0][5]); ms[1][5] = fmaf(h1, vb.y, ms[1][5]); ms[2][5] = fmaf(h2, vb.y, ms[2][5]); ms[3][5] = fmaf(h3, vb.y, ms[3][5]);
        ms[0][6] = fmaf(h0, vb.z, ms[0][6]); ms[1][6] = fmaf(h1, vb.z, ms[1][6]); ms[2][6] = fmaf(h2, vb.z, ms[2][6]); ms[3][6] = fmaf(h3, vb.z, ms[3][6]);
        ms[0][7] = fmaf(h0, vb.w, ms[0][7]); ms[1][7] = fmaf(h1, vb.w, ms[1][7]); ms[2][7] = fmaf(h2, vb.w, ms[2][7]); ms[3][7] = fmaf(h3, vb.w, ms[3][7]);
    }

#pragma unroll
    for (int h = 0; h < 8; h++) {
        float4 o = make_float4(ms[0][h], ms[1][h], ms[2][h], ms[3][h]);
        *reinterpret_cast<float4*>(logits + (((size_t)(b * NH + h) * NR + r) * NC + c0)) = o;
    }
}

// ---------------------------------------------------------------------------
// Masked softmax (exact Round-3 body). Fully-masked rows become unmasked.
// ---------------------------------------------------------------------------
__global__ __launch_bounds__(128) void softmax_kernel(
    float* __restrict__ logits, const void* __restrict__ maskv)
{
    int row = blockIdx.x;
    float* lg = logits + (size_t)row * NC;
    int tx = threadIdx.x;
    int lane = tx & 31, wid = tx >> 5;

    float4 v = reinterpret_cast<const float4*>(lg)[tx];

    uchar4 mk;
    if (g_mask_is_i32) {
        int4 t = reinterpret_cast<const int4*>(maskv)[(size_t)row * (NC / 4) + tx];
        mk = make_uchar4(t.x != 0, t.y != 0, t.z != 0, t.w != 0);
    } else {
        mk = reinterpret_cast<const uchar4*>(maskv)[(size_t)row * (NC / 4) + tx];
    }

    __shared__ float pmax[4];
    __shared__ float psum[4];
    __shared__ int pall[4];

    bool mine_all = (mk.x != 0) && (mk.y != 0) && (mk.z != 0) && (mk.w != 0);
    unsigned bal = __ballot_sync(0xffffffffu, mine_all);
    if (lane == 0) pall[wid] = (bal == 0xffffffffu) ? 1 : 0;
    __syncthreads();
    bool am = pall[0] && pall[1] && pall[2] && pall[3];

    const float NEG = __int_as_float(0xff800000);  // -inf
    float x0 = (!am && mk.x) ? NEG : v.x;
    float x1 = (!am && mk.y) ? NEG : v.y;
    float x2 = (!am && mk.z) ? NEG : v.z;
    float x3 = (!am && mk.w) ? NEG : v.w;

    float m = fmaxf(fmaxf(x0, x1), fmaxf(x2, x3));
#pragma unroll
    for (int s = 16; s > 0; s >>= 1) m = fmaxf(m, __shfl_xor_sync(0xffffffffu, m, s));
    if (lane == 0) pmax[wid] = m;
    __syncthreads();
    float rmax = fmaxf(fmaxf(pmax[0], pmax[1]), fmaxf(pmax[2], pmax[3]));

    float e0 = __expf(x0 - rmax);
    float e1 = __expf(x1 - rmax);
    float e2 = __expf(x2 - rmax);
    float e3 = __expf(x3 - rmax);

    float sm = (e0 + e1) + (e2 + e3);
#pragma unroll
    for (int s = 16; s > 0; s >>= 1) sm += __shfl_xor_sync(0xffffffffu, sm, s);
    if (lane == 0) psum[wid] = sm;
    __syncthreads();
    float inv = 1.0f / (((psum[0] + psum[1]) + (psum[2] + psum[3])));

    float4 o = make_float4(e0 * inv, e1 * inv, e2 * inv, e3 * inv);
    reinterpret_cast<float4*>(lg)[tx] = o;
}

// ---------------------------------------------------------------------------
extern "C" void kernel_launch(void* const* d_in, const int* in_sizes, int n_in,
                              void* d_out, int out_size)
{
    const float* row_emb = (const float*)d_in[0];
    const float* col_emb = (const float*)d_in[1];
    const float* cost    = (const float*)d_in[2];
    const void*  mask    = d_in[3];
    const float* Wq      = (const float*)d_in[4];
    const float* Wk      = (const float*)d_in[5];
    const float* Wv      = (const float*)d_in[6];
    const float* Wmix1   = (const float*)d_in[7];
    const float* Wmix2   = (const float*)d_in[8];
    const float* Wout    = (const float*)d_in[9];
    float* out = (float*)d_out;

    float *Q, *K, *V, *L, *AT;
    cudaGetSymbolAddress((void**)&Q,  g_Q);
    cudaGetSymbolAddress((void**)&K,  g_K);
    cudaGetSymbolAddress((void**)&V,  g_V);
    cudaGetSymbolAddress((void**)&L,  g_logits);
    cudaGetSymbolAddress((void**)&AT, g_attn);

    const size_t RE = (size_t)NR * NE;      // 262144
    const size_t RC = (size_t)NR * NC;      // 262144

    detect_mask_kernel<<<1, 1>>>((const unsigned char*)mask);

    // Q/K/V projections — TF32, K-tile 32 (384 CTAs)
    qkv_gemm_tf32<<<dim3(NE / 64, (NB * NR) / 128, 3), 256>>>(
        row_emb, col_emb, Wq, Wk, Wv, Q, K, V);

    // dot[b,h,r,c] = (1/8) * q . k — TF32 NT (1024 CTAs)
    nt_tf32<<<dim3(NC / 64, NR / 128, NB * NH), 256>>>(
        Q, K, L, ND, NE, NE, NC,
        NH, RE, (size_t)ND, RE, (size_t)ND, (size_t)NH * RC, RC,
        0.125f);

    // mix MLP — scalar (2048 CTAs), in place on L
    mix_kernel<<<NB * NR, 128>>>(cost, Wmix1, Wmix2, L);

    // masked softmax (in place on L)
    softmax_kernel<<<NB * NH * NR, 128>>>(L, mask);

    // attn @ V — TF32 NN, 64x64 tiles (256 CTAs, R11 body)
    nn_tf32<<<dim3(1, NR / 64, NB * NH), 128>>>(
        L, V, AT, NC, NC, NE, NE,
        NH, (size_t)NH * RC, RC, (size_t)NC * NE, (size_t)ND, RE, (size_t)ND);

    // final projection — TF32 NT, 64x64 tiles (256 CTAs)
    nt64_tf32<<<dim3(NE / 64, (NB * NR) / 64), 128>>>(
        AT, Wout, out, NE, NE, NE, NE);
}